// round 6
// baseline (speedup 1.0000x reference)
#include <cuda_runtime.h>
#include <cstdint>

// ---------------------------------------------------------------------------
// AttentionHead  B=8 S=4096 D=1024 DK=64
// Round 6: 512-thread CTAs (16 warps = 4/SMSP) to fix issue-latency binding.
//   attn: 8 row-groups x 2 kv-halves per CTA; cross-half softmax via smem
//         stats exchange; O halves combined once per q-tile.
//   proj: CTA tile 256x192, 128 blocks = one uniform wave.
// ---------------------------------------------------------------------------

constexpr int B  = 8;
constexpr int S  = 4096;
constexpr int D  = 1024;
constexpr int DK = 64;
constexpr int M  = B * S;

__device__ float g_Q[M * DK];
__device__ float g_K[M * DK];
__device__ float g_V[M * DK];

__device__ __forceinline__ float ex2f(float x) {
    float y; asm("ex2.approx.ftz.f32 %0, %1;" : "=f"(y) : "f"(x)); return y;
}
__device__ __forceinline__ uint32_t tf32_rna(float f) {
    uint32_t u; asm("cvt.rna.tf32.f32 %0, %1;" : "=r"(u) : "f"(f)); return u;
}
__device__ __forceinline__ uint32_t f2u(float f) { return __float_as_uint(f); }

__device__ __forceinline__ void cpa16(void* dst_smem, const void* src) {
    uint32_t a;
    asm("{ .reg .u64 t; cvta.to.shared.u64 t, %1; cvt.u32.u64 %0, t; }"
        : "=r"(a) : "l"(dst_smem));
    asm volatile("cp.async.cg.shared.global [%0], [%1], 16;" :: "r"(a), "l"(src));
}
#define CPA_COMMIT() asm volatile("cp.async.commit_group;" ::: "memory")
template <int N>
__device__ __forceinline__ void cpa_wait() {
    asm volatile("cp.async.wait_group %0;" :: "n"(N) : "memory");
}

// m16n8k8 tf32 HMMA. A row-major frag, B col-major frag, f32 accum.
__device__ __forceinline__ void mma8(float c[4], const uint32_t a[4],
                                     uint32_t b0, uint32_t b1) {
    asm volatile(
        "mma.sync.aligned.m16n8k8.row.col.f32.tf32.tf32.f32 "
        "{%0,%1,%2,%3}, {%4,%5,%6,%7}, {%8,%9}, {%0,%1,%2,%3};"
        : "+f"(c[0]), "+f"(c[1]), "+f"(c[2]), "+f"(c[3])
        : "r"(a[0]), "r"(a[1]), "r"(a[2]), "r"(a[3]), "r"(b0), "r"(b1));
}

constexpr float NEG = -1e30f;

// ---------------------------------------------------------------------------
// Phase 1: C[M,192] = X[M,1024] @ [wQ|wK|wV]^T   (1-term tf32 RNA)
// CTA 256x192, BK=32, 512 thr (16 warps: 8M x 2N, warp 32x96), 2-stage.
// ---------------------------------------------------------------------------
constexpr int PXS = 256 * 36;
constexpr int PWS = 192 * 36;
constexpr int PSTG = PXS + PWS;
constexpr int PROJ_SMEM = 2 * PSTG * 4;       // 129024 B

__global__ __launch_bounds__(512, 1)
void proj_kernel(const float* __restrict__ x,
                 const float* __restrict__ wq,
                 const float* __restrict__ wk,
                 const float* __restrict__ wv)
{
    extern __shared__ float ps[];
    const int tid  = threadIdx.x;
    const int lane = tid & 31;
    const int warp = tid >> 5;
    const int wm   = warp & 7;                // 8 M-groups of 32 rows
    const int wn   = warp >> 3;               // 2 N-groups of 96 cols
    const int m0   = blockIdx.x * 256;

    auto load_stage = [&](int st, int k0) {
        float* xs = ps + st * PSTG;
        float* ws = xs + PXS;
#pragma unroll
        for (int p = 0; p < 4; p++) {         // x: 256 rows x 32 f = 2048 chunks
            int c = tid + p * 512;
            int t = c >> 3, seg = c & 7;
            cpa16(xs + t * 36 + seg * 4, x + (size_t)(m0 + t) * D + k0 + seg * 4);
        }
#pragma unroll
        for (int p = 0; p < 3; p++) {         // w: 192 rows x 32 f = 1536 chunks
            int c = tid + p * 512;
            int n = c >> 3, seg = c & 7;
            const float* w = (n < 64) ? wq : (n < 128) ? wk : wv;
            cpa16(ws + n * 36 + seg * 4, w + (size_t)(n & 63) * D + k0 + seg * 4);
        }
        CPA_COMMIT();
    };

    float acc[2][12][4];
#pragma unroll
    for (int mt = 0; mt < 2; mt++)
#pragma unroll
        for (int nt = 0; nt < 12; nt++)
#pragma unroll
            for (int e = 0; e < 4; e++) acc[mt][nt][e] = 0.0f;

    load_stage(0, 0);

    for (int it = 0; it < 32; ++it) {
        cpa_wait<0>();
        __syncthreads();
        if (it + 1 < 32) load_stage((it + 1) & 1, (it + 1) * 32);

        const float* xs = ps + (it & 1) * PSTG;
        const float* ws = xs + PXS;
        const float* aB = xs + (wm * 32 + (lane >> 2)) * 36 + (lane & 3);
        const float* bB = ws + (wn * 96 + (lane >> 2)) * 36 + (lane & 3);

#pragma unroll
        for (int s = 0; s < 4; s++) {
            uint32_t a[2][4];
#pragma unroll
            for (int mt = 0; mt < 2; mt++) {
                const float* ap = aB + mt * 16 * 36 + s * 8;
                a[mt][0] = tf32_rna(ap[0]);
                a[mt][1] = tf32_rna(ap[8 * 36]);
                a[mt][2] = tf32_rna(ap[4]);
                a[mt][3] = tf32_rna(ap[8 * 36 + 4]);
            }
#pragma unroll
            for (int nt = 0; nt < 12; nt++) {
                const float* bp = bB + nt * 8 * 36 + s * 8;
                uint32_t b0 = tf32_rna(bp[0]);
                uint32_t b1 = tf32_rna(bp[4]);
                mma8(acc[0][nt], a[0], b0, b1);
                mma8(acc[1][nt], a[1], b0, b1);
            }
        }
        __syncthreads();
    }

    // epilogue: scale (Q only), round to tf32-exact fp32, store
    const float SC = (float)(1.4426950408889634 / 32.0);
#pragma unroll
    for (int mt = 0; mt < 2; mt++) {
#pragma unroll
        for (int nt = 0; nt < 12; nt++) {
            int col = wn * 96 + nt * 8 + 2 * (lane & 3);
            float* outp = (col < 64) ? g_Q : (col < 128) ? g_K : g_V;
            float sc = (col < 64) ? SC : 1.0f;
            int lc  = col & 63;
            int row = m0 + wm * 32 + mt * 16 + (lane >> 2);
            *(float2*)(outp + (size_t)row * DK + lc) =
                make_float2(__uint_as_float(tf32_rna(acc[mt][nt][0] * sc)),
                            __uint_as_float(tf32_rna(acc[mt][nt][1] * sc)));
            *(float2*)(outp + (size_t)(row + 8) * DK + lc) =
                make_float2(__uint_as_float(tf32_rna(acc[mt][nt][2] * sc)),
                            __uint_as_float(tf32_rna(acc[mt][nt][3] * sc)));
        }
    }
}

// ---------------------------------------------------------------------------
// Phase 2: flash attention, 512 thr (16 warps: 8 row-groups x 2 kv-halves).
// Warp tile: 16 q-rows x 64 kv cols. Cross-half softmax stats via smem.
// O halves combined once per q-tile. Causal-paired q-tiles, 128 blocks.
// ---------------------------------------------------------------------------
constexpr int KSZ  = 128 * 68;
constexpr int VSZ  = 128 * 72;
constexpr int STG  = KSZ + VSZ;
constexpr int POFF = 2 * STG;
constexpr int ATTN_SMEM = (POFF + 128 * 132) * 4;  // 210944 B

__global__ __launch_bounds__(512, 1)
void attn_kernel(float* __restrict__ out)
{
    extern __shared__ float sm[];
    __shared__ float Smx[2][128];
    __shared__ float Srs[2][128];

    const int b    = blockIdx.y;
    const int pj   = blockIdx.x;
    const int tid  = threadIdx.x;
    const int lane = tid & 31;
    const int warp = tid >> 5;
    const int wr   = warp >> 1;               // row group 0..7
    const int wc   = warp & 1;                // kv half 0..1
    const int wb   = wr * 16;                 // q-row base in tile
    const int kb   = wc * 64;                 // kv-col base in tile
    const int p4   = lane >> 2;
    const int q4   = lane & 3;

    float* Ps = sm + POFF;

    auto load_kv = [&](int kt, int st) {
        float* Ks = sm + st * STG;
        float* Vs = Ks + KSZ;
        const int t0 = kt * 128;
#pragma unroll
        for (int p = 0; p < 4; p++) {
            int c = tid + p * 512;
            int t = c >> 4, seg = c & 15;
            cpa16(Ks + t * 68 + seg * 4, g_K + ((size_t)(b * S + t0 + t)) * 64 + seg * 4);
        }
#pragma unroll
        for (int p = 0; p < 4; p++) {
            int c = tid + p * 512;
            int t = c >> 4, seg = c & 15;
            cpa16(Vs + t * 72 + seg * 4, g_V + ((size_t)(b * S + t0 + t)) * 64 + seg * 4);
        }
        CPA_COMMIT();
    };

    for (int qsel = 0; qsel < 2; qsel++) {
        const int qt = qsel ? (31 - pj) : pj;
        const int q0 = qt * 128;
        const int nt = qt + 1;

        load_kv(0, 0);

        // Q a-frags (tf32-exact bits)
        uint32_t qa[8][4];
#pragma unroll
        for (int s = 0; s < 8; s++) {
            const float* qp = g_Q + ((size_t)(b * S + q0 + wb + p4)) * 64 + s * 8 + q4;
            qa[s][0] = f2u(qp[0]);
            qa[s][1] = f2u(qp[8 * 64]);
            qa[s][2] = f2u(qp[4]);
            qa[s][3] = f2u(qp[8 * 64 + 4]);
        }

        float of[8][4];
        float m0r = NEG, m1r = NEG, l0 = 0.0f, l1 = 0.0f;
#pragma unroll
        for (int j = 0; j < 8; j++)
#pragma unroll
            for (int e = 0; e < 4; e++) of[j][e] = 0.0f;

        for (int it = 0; it < nt; ++it) {
            const int st = it & 1;
            cpa_wait<0>();
            __syncthreads();                              // BAR A: stage ready, prev PV done
            if (it + 1 < nt) load_kv(it + 1, st ^ 1);

            const float* Ks = sm + st * STG;
            const float* Vs = Ks + KSZ;

            // ---- S = Q K^T  (16 rows x own 64 kv cols) ----
            float sf[8][4];
#pragma unroll
            for (int j = 0; j < 8; j++)
#pragma unroll
                for (int e = 0; e < 4; e++) sf[j][e] = 0.0f;

            const float* kB = Ks + (kb + p4) * 68 + q4;
#pragma unroll 4
            for (int j = 0; j < 8; j++) {
                const float* kp = kB + j * 8 * 68;
#pragma unroll
                for (int s = 0; s < 8; s++)
                    mma8(sf[j], qa[s], f2u(kp[s * 8]), f2u(kp[s * 8 + 4]));
            }

            // ---- causal mask on diagonal tile ----
            if (it == qt) {
                int r0 = wb + p4;
#pragma unroll
                for (int j = 0; j < 8; j++) {
                    int c0 = kb + j * 8 + 2 * q4;
                    if (c0     > r0)     sf[j][0] = NEG;
                    if (c0 + 1 > r0)     sf[j][1] = NEG;
                    if (c0     > r0 + 8) sf[j][2] = NEG;
                    if (c0 + 1 > r0 + 8) sf[j][3] = NEG;
                }
            }

            // ---- local max + cross-half combine ----
            float mx0 = NEG, mx1 = NEG;
#pragma unroll
            for (int j = 0; j < 8; j++) {
                mx0 = fmaxf(mx0, fmaxf(sf[j][0], sf[j][1]));
                mx1 = fmaxf(mx1, fmaxf(sf[j][2], sf[j][3]));
            }
            mx0 = fmaxf(mx0, __shfl_xor_sync(0xffffffffu, mx0, 1));
            mx0 = fmaxf(mx0, __shfl_xor_sync(0xffffffffu, mx0, 2));
            mx1 = fmaxf(mx1, __shfl_xor_sync(0xffffffffu, mx1, 1));
            mx1 = fmaxf(mx1, __shfl_xor_sync(0xffffffffu, mx1, 2));
            if (q4 == 0) {
                Smx[wc][wb + p4]     = mx0;
                Smx[wc][wb + p4 + 8] = mx1;
            }
            __syncthreads();                              // BAR B
            mx0 = fmaxf(mx0, Smx[wc ^ 1][wb + p4]);
            mx1 = fmaxf(mx1, Smx[wc ^ 1][wb + p4 + 8]);
            float mn0 = fmaxf(m0r, mx0), mn1 = fmaxf(m1r, mx1);
            float al0 = ex2f(m0r - mn0), al1 = ex2f(m1r - mn1);
            m0r = mn0; m1r = mn1;

            // ---- exp (tf32-rounded), P store, partial row sums ----
            float rs0 = 0.0f, rs1 = 0.0f;
            float* pw = Ps + (wb + p4) * 132 + kb + 2 * q4;
#pragma unroll
            for (int j = 0; j < 8; j++) {
                float p00 = __uint_as_float(tf32_rna(ex2f(sf[j][0] - mn0)));
                float p01 = __uint_as_float(tf32_rna(ex2f(sf[j][1] - mn0)));
                float p10 = __uint_as_float(tf32_rna(ex2f(sf[j][2] - mn1)));
                float p11 = __uint_as_float(tf32_rna(ex2f(sf[j][3] - mn1)));
                rs0 += p00 + p01;
                rs1 += p10 + p11;
                *(float2*)(pw + j * 8)           = make_float2(p00, p01);
                *(float2*)(pw + 8 * 132 + j * 8) = make_float2(p10, p11);
            }
            rs0 += __shfl_xor_sync(0xffffffffu, rs0, 1);
            rs0 += __shfl_xor_sync(0xffffffffu, rs0, 2);
            rs1 += __shfl_xor_sync(0xffffffffu, rs1, 1);
            rs1 += __shfl_xor_sync(0xffffffffu, rs1, 2);
            if (q4 == 0) {
                Srs[wc][wb + p4]     = rs0;
                Srs[wc][wb + p4 + 8] = rs1;
            }
            __syncthreads();                              // BAR C
            rs0 += Srs[wc ^ 1][wb + p4];
            rs1 += Srs[wc ^ 1][wb + p4 + 8];
            l0 = l0 * al0 + rs0;
            l1 = l1 * al1 + rs1;
#pragma unroll
            for (int j = 0; j < 8; j++) {
                of[j][0] *= al0; of[j][1] *= al0;
                of[j][2] *= al1; of[j][3] *= al1;
            }

            // ---- O += P V over own kv half (warp-private P) ----
            const float* pA = Ps + (wb + p4) * 132 + kb + q4;
            const float* vB = Vs + (kb + q4) * 72 + p4;
#pragma unroll 4
            for (int s2 = 0; s2 < 8; s2++) {
                uint32_t pa[4];
                pa[0] = f2u(pA[s2 * 8]);
                pa[1] = f2u(pA[8 * 132 + s2 * 8]);
                pa[2] = f2u(pA[s2 * 8 + 4]);
                pa[3] = f2u(pA[8 * 132 + s2 * 8 + 4]);
                const float* vp = vB + s2 * 8 * 72;
#pragma unroll
                for (int j2 = 0; j2 < 8; j2++)
                    mma8(of[j2], pa, f2u(vp[j2 * 8]), f2u(vp[4 * 72 + j2 * 8]));
            }
        }

        // ---- combine O halves via smem (reuse P region) ----
        __syncthreads();                                  // all PV done
        if (wc == 1) {
            float* cb = Ps + (wb + p4) * 132 + 2 * q4;
#pragma unroll
            for (int j2 = 0; j2 < 8; j2++) {
                *(float2*)(cb + j2 * 8)           = make_float2(of[j2][0], of[j2][1]);
                *(float2*)(cb + 8 * 132 + j2 * 8) = make_float2(of[j2][2], of[j2][3]);
            }
        }
        __syncthreads();
        if (wc == 0) {
            const float* cb = Ps + (wb + p4) * 132 + 2 * q4;
            float inv0 = 1.0f / l0, inv1 = 1.0f / l1;
            float* orow0 = out + ((size_t)(b * S + q0 + wb + p4)) * 64 + 2 * q4;
            float* orow1 = orow0 + 8 * 64;
#pragma unroll
            for (int j2 = 0; j2 < 8; j2++) {
                float2 c0 = *(const float2*)(cb + j2 * 8);
                float2 c1 = *(const float2*)(cb + 8 * 132 + j2 * 8);
                *(float2*)(orow0 + j2 * 8) =
                    make_float2((of[j2][0] + c0.x) * inv0, (of[j2][1] + c0.y) * inv0);
                *(float2*)(orow1 + j2 * 8) =
                    make_float2((of[j2][2] + c1.x) * inv1, (of[j2][3] + c1.y) * inv1);
            }
        }
        __syncthreads();                                  // Ps free for next q-tile
    }
}

// ---------------------------------------------------------------------------
extern "C" void kernel_launch(void* const* d_in, const int* in_sizes, int n_in,
                              void* d_out, int out_size)
{
    const float* x  = (const float*)d_in[0];
    const float* wq = (const float*)d_in[1];
    const float* wk = (const float*)d_in[2];
    const float* wv = (const float*)d_in[3];
    float* out = (float*)d_out;

    cudaFuncSetAttribute(proj_kernel,
                         cudaFuncAttributeMaxDynamicSharedMemorySize, PROJ_SMEM);
    cudaFuncSetAttribute(attn_kernel,
                         cudaFuncAttributeMaxDynamicSharedMemorySize, ATTN_SMEM);

    proj_kernel<<<M / 256, 512, PROJ_SMEM>>>(x, wq, wk, wv);
    attn_kernel<<<dim3(16, B), 512, ATTN_SMEM>>>(out);
}

// round 7
// speedup vs baseline: 1.2945x; 1.2945x over previous
#include <cuda_runtime.h>
#include <cstdint>

// ---------------------------------------------------------------------------
// AttentionHead  B=8 S=4096 D=1024 DK=64
// Round 7: crossbar-bound fix. Pair-permuted scratch layouts so every HMMA
// operand load is LDS.64 and P softmax-store is STS.128:
//   g_Q/g_K: dk permuted within 8-groups -> (k,k+4) adjacent.
//   g_V:     stored transposed [b][dk][t], t pair-permuted.
//   P smem:  interleaved (row-half bit in LSB) -> STS.128 / LDS.64.
// QK mma loop reordered (s outer) for independent accumulator chains.
// ---------------------------------------------------------------------------

constexpr int B  = 8;
constexpr int S  = 4096;
constexpr int D  = 1024;
constexpr int DK = 64;
constexpr int M  = B * S;

__device__ float g_Q[M * DK];
__device__ float g_K[M * DK];
__device__ float g_V[M * DK];   // used as [B][64][4096], t pair-permuted

__device__ __forceinline__ float ex2f(float x) {
    float y; asm("ex2.approx.ftz.f32 %0, %1;" : "=f"(y) : "f"(x)); return y;
}
__device__ __forceinline__ uint32_t tf32_rna(float f) {
    uint32_t u; asm("cvt.rna.tf32.f32 %0, %1;" : "=r"(u) : "f"(f)); return u;
}
__device__ __forceinline__ float tf32ef(float f) {
    return __uint_as_float(tf32_rna(f));
}
__device__ __forceinline__ uint32_t f2u(float f) { return __float_as_uint(f); }

// pair permutation within an 8-group: (u,u+4) -> (2u, 2u+1)
__host__ __device__ __forceinline__ int perm8(int u) {
    return 2 * (u & 3) + ((u >> 2) & 1);
}

__device__ __forceinline__ void cpa16(void* dst_smem, const void* src) {
    uint32_t a;
    asm("{ .reg .u64 t; cvta.to.shared.u64 t, %1; cvt.u32.u64 %0, t; }"
        : "=r"(a) : "l"(dst_smem));
    asm volatile("cp.async.cg.shared.global [%0], [%1], 16;" :: "r"(a), "l"(src));
}
#define CPA_COMMIT() asm volatile("cp.async.commit_group;" ::: "memory")
template <int N>
__device__ __forceinline__ void cpa_wait() {
    asm volatile("cp.async.wait_group %0;" :: "n"(N) : "memory");
}

// m16n8k8 tf32 HMMA. A row-major frag, B col-major frag, f32 accum.
__device__ __forceinline__ void mma8(float c[4], const uint32_t a[4],
                                     uint32_t b0, uint32_t b1) {
    asm volatile(
        "mma.sync.aligned.m16n8k8.row.col.f32.tf32.tf32.f32 "
        "{%0,%1,%2,%3}, {%4,%5,%6,%7}, {%8,%9}, {%0,%1,%2,%3};"
        : "+f"(c[0]), "+f"(c[1]), "+f"(c[2]), "+f"(c[3])
        : "r"(a[0]), "r"(a[1]), "r"(a[2]), "r"(a[3]), "r"(b0), "r"(b1));
}

constexpr float NEG = -1e30f;

// ---------------------------------------------------------------------------
// Phase 1: C[M,192] = X[M,1024] @ [wQ|wK|wV]^T   (1-term tf32 RNA)
// CTA 256x192, BK=32, 512 thr. Epilogue writes permuted scratch layouts.
// ---------------------------------------------------------------------------
constexpr int PXS = 256 * 36;
constexpr int PWS = 192 * 36;
constexpr int PSTG = PXS + PWS;
constexpr int PROJ_SMEM = 2 * PSTG * 4;       // 129024 B

__global__ __launch_bounds__(512, 1)
void proj_kernel(const float* __restrict__ x,
                 const float* __restrict__ wq,
                 const float* __restrict__ wk,
                 const float* __restrict__ wv)
{
    extern __shared__ float ps[];
    const int tid  = threadIdx.x;
    const int lane = tid & 31;
    const int warp = tid >> 5;
    const int wm   = warp & 7;
    const int wn   = warp >> 3;
    const int m0   = blockIdx.x * 256;

    auto load_stage = [&](int st, int k0) {
        float* xs = ps + st * PSTG;
        float* ws = xs + PXS;
#pragma unroll
        for (int p = 0; p < 4; p++) {
            int c = tid + p * 512;
            int t = c >> 3, seg = c & 7;
            cpa16(xs + t * 36 + seg * 4, x + (size_t)(m0 + t) * D + k0 + seg * 4);
        }
#pragma unroll
        for (int p = 0; p < 3; p++) {
            int c = tid + p * 512;
            int n = c >> 3, seg = c & 7;
            const float* w = (n < 64) ? wq : (n < 128) ? wk : wv;
            cpa16(ws + n * 36 + seg * 4, w + (size_t)(n & 63) * D + k0 + seg * 4);
        }
        CPA_COMMIT();
    };

    float acc[2][12][4];
#pragma unroll
    for (int mt = 0; mt < 2; mt++)
#pragma unroll
        for (int nt = 0; nt < 12; nt++)
#pragma unroll
            for (int e = 0; e < 4; e++) acc[mt][nt][e] = 0.0f;

    load_stage(0, 0);

    for (int it = 0; it < 32; ++it) {
        cpa_wait<0>();
        __syncthreads();
        if (it + 1 < 32) load_stage((it + 1) & 1, (it + 1) * 32);

        const float* xs = ps + (it & 1) * PSTG;
        const float* ws = xs + PXS;
        const float* aB = xs + (wm * 32 + (lane >> 2)) * 36 + (lane & 3);
        const float* bB = ws + (wn * 96 + (lane >> 2)) * 36 + (lane & 3);

#pragma unroll
        for (int s = 0; s < 4; s++) {
            uint32_t a[2][4];
#pragma unroll
            for (int mt = 0; mt < 2; mt++) {
                const float* ap = aB + mt * 16 * 36 + s * 8;
                a[mt][0] = tf32_rna(ap[0]);
                a[mt][1] = tf32_rna(ap[8 * 36]);
                a[mt][2] = tf32_rna(ap[4]);
                a[mt][3] = tf32_rna(ap[8 * 36 + 4]);
            }
#pragma unroll
            for (int nt = 0; nt < 12; nt++) {
                const float* bp = bB + nt * 8 * 36 + s * 8;
                uint32_t b0 = tf32_rna(bp[0]);
                uint32_t b1 = tf32_rna(bp[4]);
                mma8(acc[0][nt], a[0], b0, b1);
                mma8(acc[1][nt], a[1], b0, b1);
            }
        }
        __syncthreads();
    }

    // epilogue: Q scaled; all outputs tf32-exact; permuted layouts.
    const float SC = (float)(1.4426950408889634 / 32.0);
#pragma unroll
    for (int mt = 0; mt < 2; mt++) {
#pragma unroll
        for (int nt = 0; nt < 12; nt++) {
            int col = wn * 96 + nt * 8 + 2 * (lane & 3);
            int row = m0 + wm * 32 + mt * 16 + (lane >> 2);
            if (col < 128) {
                // Q / K: dk pair-permuted columns
                float* outp = (col < 64) ? g_Q : g_K;
                float sc = (col < 64) ? SC : 1.0f;
                int b8  = (col & 63) & ~7;
                int p0  = b8 | perm8(col & 7);
                int p1  = b8 | perm8((col + 1) & 7);
                outp[(size_t)row * DK + p0]       = tf32ef(acc[mt][nt][0] * sc);
                outp[(size_t)row * DK + p1]       = tf32ef(acc[mt][nt][1] * sc);
                outp[(size_t)(row + 8) * DK + p0] = tf32ef(acc[mt][nt][2] * sc);
                outp[(size_t)(row + 8) * DK + p1] = tf32ef(acc[mt][nt][3] * sc);
            } else {
                // V: transposed [b][dk][t], t pair-permuted
                int lc = col & 63;
                int b0r = row >> 12,  s0 = row & 4095;
                int b1r = (row + 8) >> 12, s1 = (row + 8) & 4095;
                size_t pt0 = (size_t)(s0 & ~7) | perm8(s0 & 7);
                size_t pt1 = (size_t)(s1 & ~7) | perm8(s1 & 7);
                g_V[((size_t)b0r * 64 + lc)     * 4096 + pt0] = tf32ef(acc[mt][nt][0]);
                g_V[((size_t)b0r * 64 + lc + 1) * 4096 + pt0] = tf32ef(acc[mt][nt][1]);
                g_V[((size_t)b1r * 64 + lc)     * 4096 + pt1] = tf32ef(acc[mt][nt][2]);
                g_V[((size_t)b1r * 64 + lc + 1) * 4096 + pt1] = tf32ef(acc[mt][nt][3]);
            }
        }
    }
}

// ---------------------------------------------------------------------------
// Phase 2: flash attention. 512 thr (8 row-groups x 2 kv-halves).
// K smem [t][dk_perm] stride 72; VT smem [dk][t_perm] stride 136;
// P smem interleaved: addr(r,c) = RB*264 + 2c + h, RB = (r&7)+(r>>4)*8,
// h = (r>>3)&1  ->  STS.128 write, LDS.64 A-frag reads.
// ---------------------------------------------------------------------------
constexpr int KSZ  = 128 * 72;                // 9216 floats
constexpr int VTSZ = 64 * 136;                // 8704 floats
constexpr int STG  = KSZ + VTSZ;              // 17920
constexpr int POFF = 2 * STG;                 // 35840
constexpr int PSZ  = 64 * 264;                // 16896
constexpr int ATTN_SMEM = (POFF + PSZ) * 4;   // 210944 B

__global__ __launch_bounds__(512, 1)
void attn_kernel(float* __restrict__ out)
{
    extern __shared__ float sm[];
    __shared__ float Smx[2][128];
    __shared__ float Srs[2][128];

    const int b    = blockIdx.y;
    const int pj   = blockIdx.x;
    const int tid  = threadIdx.x;
    const int lane = tid & 31;
    const int warp = tid >> 5;
    const int wr   = warp >> 1;               // row group 0..7
    const int wc   = warp & 1;                // kv half 0..1
    const int wb   = wr * 16;
    const int kb   = wc * 64;
    const int p4   = lane >> 2;
    const int q4   = lane & 3;
    const int RB   = p4 + wr * 8;             // P row-block index

    float* Ps = sm + POFF;

    auto load_kv = [&](int kt, int st) {
        float* Ks  = sm + st * STG;
        float* VTs = Ks + KSZ;
        const int t0 = kt * 128;
#pragma unroll
        for (int p = 0; p < 4; p++) {         // K: 128 t-rows x 64 dk
            int c = tid + p * 512;
            int t = c >> 4, seg = c & 15;
            cpa16(Ks + t * 72 + seg * 4,
                  g_K + ((size_t)(b * S + t0 + t)) * 64 + seg * 4);
        }
#pragma unroll
        for (int p = 0; p < 4; p++) {         // VT: 64 dk-rows x 128 t
            int c = tid + p * 512;
            int dk = c >> 5, ch = c & 31;
            cpa16(VTs + dk * 136 + ch * 4,
                  g_V + ((size_t)b * 64 + dk) * 4096 + t0 + ch * 4);
        }
        CPA_COMMIT();
    };

    for (int qsel = 0; qsel < 2; qsel++) {
        const int qt = qsel ? (31 - pj) : pj;
        const int q0 = qt * 128;
        const int nt = qt + 1;

        load_kv(0, 0);

        // Q a-frags: permuted columns -> float2 loads; {lo.x,hi.x,lo.y,hi.y}
        uint32_t qa[8][4];
#pragma unroll
        for (int s = 0; s < 8; s++) {
            const float* qp = g_Q + ((size_t)(b * S + q0 + wb + p4)) * 64 + s * 8 + 2 * q4;
            float2 lo = *(const float2*)qp;
            float2 hi = *(const float2*)(qp + 8 * 64);
            qa[s][0] = f2u(lo.x);
            qa[s][1] = f2u(hi.x);
            qa[s][2] = f2u(lo.y);
            qa[s][3] = f2u(hi.y);
        }

        float of[8][4];
        float m0r = NEG, m1r = NEG, l0 = 0.0f, l1 = 0.0f;
#pragma unroll
        for (int j = 0; j < 8; j++)
#pragma unroll
            for (int e = 0; e < 4; e++) of[j][e] = 0.0f;

        for (int it = 0; it < nt; ++it) {
            const int st = it & 1;
            cpa_wait<0>();
            __syncthreads();                  // stage ready, prev PV done
            if (it + 1 < nt) load_kv(it + 1, st ^ 1);

            const float* Ks  = sm + st * STG;
            const float* VTs = Ks + KSZ;

            // ---- S = Q K^T (s outer -> 8 independent chains) ----
            float sf[8][4];
#pragma unroll
            for (int j = 0; j < 8; j++)
#pragma unroll
                for (int e = 0; e < 4; e++) sf[j][e] = 0.0f;

            const float* kB = Ks + (kb + p4) * 72 + 2 * q4;
#pragma unroll
            for (int s = 0; s < 8; s++) {
                const float* kp = kB + s * 8;
#pragma unroll
                for (int j = 0; j < 8; j++) {
                    float2 kv2 = *(const float2*)(kp + j * 8 * 72);
                    mma8(sf[j], qa[s], f2u(kv2.x), f2u(kv2.y));
                }
            }

            // ---- causal mask on diagonal tile ----
            if (it == qt) {
                int r0 = wb + p4;
#pragma unroll
                for (int j = 0; j < 8; j++) {
                    int c0 = kb + j * 8 + 2 * q4;
                    if (c0     > r0)     sf[j][0] = NEG;
                    if (c0 + 1 > r0)     sf[j][1] = NEG;
                    if (c0     > r0 + 8) sf[j][2] = NEG;
                    if (c0 + 1 > r0 + 8) sf[j][3] = NEG;
                }
            }

            // ---- local max + cross-half combine ----
            float mx0 = NEG, mx1 = NEG;
#pragma unroll
            for (int j = 0; j < 8; j++) {
                mx0 = fmaxf(mx0, fmaxf(sf[j][0], sf[j][1]));
                mx1 = fmaxf(mx1, fmaxf(sf[j][2], sf[j][3]));
            }
            mx0 = fmaxf(mx0, __shfl_xor_sync(0xffffffffu, mx0, 1));
            mx0 = fmaxf(mx0, __shfl_xor_sync(0xffffffffu, mx0, 2));
            mx1 = fmaxf(mx1, __shfl_xor_sync(0xffffffffu, mx1, 1));
            mx1 = fmaxf(mx1, __shfl_xor_sync(0xffffffffu, mx1, 2));
            if (q4 == 0) {
                Smx[wc][wb + p4]     = mx0;
                Smx[wc][wb + p4 + 8] = mx1;
            }
            __syncthreads();
            mx0 = fmaxf(mx0, Smx[wc ^ 1][wb + p4]);
            mx1 = fmaxf(mx1, Smx[wc ^ 1][wb + p4 + 8]);
            float mn0 = fmaxf(m0r, mx0), mn1 = fmaxf(m1r, mx1);
            float al0 = ex2f(m0r - mn0), al1 = ex2f(m1r - mn1);
            m0r = mn0; m1r = mn1;

            // ---- exp, P store (STS.128, interleaved layout), row sums ----
            float rs0 = 0.0f, rs1 = 0.0f;
            float* pw = Ps + RB * 264 + (kb + 2 * q4) * 2;
#pragma unroll
            for (int j = 0; j < 8; j++) {
                float p00 = tf32ef(ex2f(sf[j][0] - mn0));   // (r,   c)
                float p01 = tf32ef(ex2f(sf[j][1] - mn0));   // (r,   c+1)
                float p10 = tf32ef(ex2f(sf[j][2] - mn1));   // (r+8, c)
                float p11 = tf32ef(ex2f(sf[j][3] - mn1));   // (r+8, c+1)
                rs0 += p00 + p01;
                rs1 += p10 + p11;
                *(float4*)(pw + j * 16) = make_float4(p00, p10, p01, p11);
            }
            rs0 += __shfl_xor_sync(0xffffffffu, rs0, 1);
            rs0 += __shfl_xor_sync(0xffffffffu, rs0, 2);
            rs1 += __shfl_xor_sync(0xffffffffu, rs1, 1);
            rs1 += __shfl_xor_sync(0xffffffffu, rs1, 2);
            if (q4 == 0) {
                Srs[wc][wb + p4]     = rs0;
                Srs[wc][wb + p4 + 8] = rs1;
            }
            __syncthreads();
            rs0 += Srs[wc ^ 1][wb + p4];
            rs1 += Srs[wc ^ 1][wb + p4 + 8];
            l0 = l0 * al0 + rs0;
            l1 = l1 * al1 + rs1;
#pragma unroll
            for (int j = 0; j < 8; j++) {
                of[j][0] *= al0; of[j][1] *= al0;
                of[j][2] *= al1; of[j][3] *= al1;
            }

            // ---- O += P V over own kv half ----
            // A-frags: 2x LDS.64 from interleaved P; B-frags: LDS.64 from VT.
            const float* pA = Ps + RB * 264 + (kb + q4) * 2;
            const float* vB = VTs + p4 * 136 + kb + 2 * q4;
#pragma unroll
            for (int s2 = 0; s2 < 8; s2++) {
                uint32_t pa[4];
                float2 pa01 = *(const float2*)(pA + s2 * 16);
                float2 pa23 = *(const float2*)(pA + s2 * 16 + 8);
                pa[0] = f2u(pa01.x); pa[1] = f2u(pa01.y);
                pa[2] = f2u(pa23.x); pa[3] = f2u(pa23.y);
                const float* vp = vB + s2 * 8;
#pragma unroll
                for (int j2 = 0; j2 < 8; j2++) {
                    float2 vv = *(const float2*)(vp + j2 * 8 * 136);
                    mma8(of[j2], pa, f2u(vv.x), f2u(vv.y));
                }
            }
        }

        // ---- combine O halves via smem (reuse P region as scratch) ----
        __syncthreads();
        if (wc == 1) {
            float* cb = Ps + (wb + p4) * 132 + 2 * q4;
#pragma unroll
            for (int j2 = 0; j2 < 8; j2++) {
                *(float2*)(cb + j2 * 8)           = make_float2(of[j2][0], of[j2][1]);
                *(float2*)(cb + 8 * 132 + j2 * 8) = make_float2(of[j2][2], of[j2][3]);
            }
        }
        __syncthreads();
        if (wc == 0) {
            const float* cb = Ps + (wb + p4) * 132 + 2 * q4;
            float inv0 = 1.0f / l0, inv1 = 1.0f / l1;
            float* orow0 = out + ((size_t)(b * S + q0 + wb + p4)) * 64 + 2 * q4;
            float* orow1 = orow0 + 8 * 64;
#pragma unroll
            for (int j2 = 0; j2 < 8; j2++) {
                float2 c0 = *(const float2*)(cb + j2 * 8);
                float2 c1 = *(const float2*)(cb + 8 * 132 + j2 * 8);
                *(float2*)(orow0 + j2 * 8) =
                    make_float2((of[j2][0] + c0.x) * inv0, (of[j2][1] + c0.y) * inv0);
                *(float2*)(orow1 + j2 * 8) =
                    make_float2((of[j2][2] + c1.x) * inv1, (of[j2][3] + c1.y) * inv1);
            }
        }
        __syncthreads();
    }
}

// ---------------------------------------------------------------------------
extern "C" void kernel_launch(void* const* d_in, const int* in_sizes, int n_in,
                              void* d_out, int out_size)
{
    const float* x  = (const float*)d_in[0];
    const float* wq = (const float*)d_in[1];
    const float* wk = (const float*)d_in[2];
    const float* wv = (const float*)d_in[3];
    float* out = (float*)d_out;

    cudaFuncSetAttribute(proj_kernel,
                         cudaFuncAttributeMaxDynamicSharedMemorySize, PROJ_SMEM);
    cudaFuncSetAttribute(attn_kernel,
                         cudaFuncAttributeMaxDynamicSharedMemorySize, ATTN_SMEM);

    proj_kernel<<<M / 256, 512, PROJ_SMEM>>>(x, wq, wk, wv);
    attn_kernel<<<dim3(16, B), 512, ATTN_SMEM>>>(out);
}

// round 8
// speedup vs baseline: 1.3237x; 1.0226x over previous
#include <cuda_runtime.h>
#include <cstdint>

// ---------------------------------------------------------------------------
// AttentionHead  B=8 S=4096 D=1024 DK=64
// Round 8: split-KV per-warp accumulators -> 1 barrier/tile (was 3).
// Each (row-group x kv-half) warp keeps private (m,l,O); halves merged once
// per q-tile with exact LSE combine. Layouts from R7 (all LDS.64/STS.128).
// ---------------------------------------------------------------------------

constexpr int B  = 8;
constexpr int S  = 4096;
constexpr int D  = 1024;
constexpr int DK = 64;
constexpr int M  = B * S;

__device__ float g_Q[M * DK];
__device__ float g_K[M * DK];
__device__ float g_V[M * DK];   // used as [B][64][4096], t pair-permuted

__device__ __forceinline__ float ex2f(float x) {
    float y; asm("ex2.approx.ftz.f32 %0, %1;" : "=f"(y) : "f"(x)); return y;
}
__device__ __forceinline__ uint32_t tf32_rna(float f) {
    uint32_t u; asm("cvt.rna.tf32.f32 %0, %1;" : "=r"(u) : "f"(f)); return u;
}
__device__ __forceinline__ float tf32ef(float f) {
    return __uint_as_float(tf32_rna(f));
}
__device__ __forceinline__ uint32_t f2u(float f) { return __float_as_uint(f); }

// pair permutation within an 8-group: (u,u+4) -> (2u, 2u+1)
__host__ __device__ __forceinline__ int perm8(int u) {
    return 2 * (u & 3) + ((u >> 2) & 1);
}

__device__ __forceinline__ void cpa16(void* dst_smem, const void* src) {
    uint32_t a;
    asm("{ .reg .u64 t; cvta.to.shared.u64 t, %1; cvt.u32.u64 %0, t; }"
        : "=r"(a) : "l"(dst_smem));
    asm volatile("cp.async.cg.shared.global [%0], [%1], 16;" :: "r"(a), "l"(src));
}
#define CPA_COMMIT() asm volatile("cp.async.commit_group;" ::: "memory")
template <int N>
__device__ __forceinline__ void cpa_wait() {
    asm volatile("cp.async.wait_group %0;" :: "n"(N) : "memory");
}

// m16n8k8 tf32 HMMA. A row-major frag, B col-major frag, f32 accum.
__device__ __forceinline__ void mma8(float c[4], const uint32_t a[4],
                                     uint32_t b0, uint32_t b1) {
    asm volatile(
        "mma.sync.aligned.m16n8k8.row.col.f32.tf32.tf32.f32 "
        "{%0,%1,%2,%3}, {%4,%5,%6,%7}, {%8,%9}, {%0,%1,%2,%3};"
        : "+f"(c[0]), "+f"(c[1]), "+f"(c[2]), "+f"(c[3])
        : "r"(a[0]), "r"(a[1]), "r"(a[2]), "r"(a[3]), "r"(b0), "r"(b1));
}

constexpr float NEG = -1e30f;

// ---------------------------------------------------------------------------
// Phase 1: C[M,192] = X[M,1024] @ [wQ|wK|wV]^T   (1-term tf32 RNA)
// CTA 256x192, BK=32, 512 thr. One __syncthreads per iter. Epilogue writes
// pair-permuted scratch layouts (Q/K dk-perm; V transposed + t-perm).
// ---------------------------------------------------------------------------
constexpr int PXS = 256 * 36;
constexpr int PWS = 192 * 36;
constexpr int PSTG = PXS + PWS;
constexpr int PROJ_SMEM = 2 * PSTG * 4;       // 129024 B

__global__ __launch_bounds__(512, 1)
void proj_kernel(const float* __restrict__ x,
                 const float* __restrict__ wq,
                 const float* __restrict__ wk,
                 const float* __restrict__ wv)
{
    extern __shared__ float ps[];
    const int tid  = threadIdx.x;
    const int lane = tid & 31;
    const int warp = tid >> 5;
    const int wm   = warp & 7;
    const int wn   = warp >> 3;
    const int m0   = blockIdx.x * 256;

    auto load_stage = [&](int st, int k0) {
        float* xs = ps + st * PSTG;
        float* ws = xs + PXS;
#pragma unroll
        for (int p = 0; p < 4; p++) {
            int c = tid + p * 512;
            int t = c >> 3, seg = c & 7;
            cpa16(xs + t * 36 + seg * 4, x + (size_t)(m0 + t) * D + k0 + seg * 4);
        }
#pragma unroll
        for (int p = 0; p < 3; p++) {
            int c = tid + p * 512;
            int n = c >> 3, seg = c & 7;
            const float* w = (n < 64) ? wq : (n < 128) ? wk : wv;
            cpa16(ws + n * 36 + seg * 4, w + (size_t)(n & 63) * D + k0 + seg * 4);
        }
        CPA_COMMIT();
    };

    float acc[2][12][4];
#pragma unroll
    for (int mt = 0; mt < 2; mt++)
#pragma unroll
        for (int nt = 0; nt < 12; nt++)
#pragma unroll
            for (int e = 0; e < 4; e++) acc[mt][nt][e] = 0.0f;

    load_stage(0, 0);

    for (int it = 0; it < 32; ++it) {
        cpa_wait<0>();
        __syncthreads();                       // retires MMA(it-1) reads too
        if (it + 1 < 32) load_stage((it + 1) & 1, (it + 1) * 32);

        const float* xs = ps + (it & 1) * PSTG;
        const float* ws = xs + PXS;
        const float* aB = xs + (wm * 32 + (lane >> 2)) * 36 + (lane & 3);
        const float* bB = ws + (wn * 96 + (lane >> 2)) * 36 + (lane & 3);

#pragma unroll
        for (int s = 0; s < 4; s++) {
            uint32_t a[2][4];
#pragma unroll
            for (int mt = 0; mt < 2; mt++) {
                const float* ap = aB + mt * 16 * 36 + s * 8;
                a[mt][0] = tf32_rna(ap[0]);
                a[mt][1] = tf32_rna(ap[8 * 36]);
                a[mt][2] = tf32_rna(ap[4]);
                a[mt][3] = tf32_rna(ap[8 * 36 + 4]);
            }
#pragma unroll
            for (int nt = 0; nt < 12; nt++) {
                const float* bp = bB + nt * 8 * 36 + s * 8;
                uint32_t b0 = tf32_rna(bp[0]);
                uint32_t b1 = tf32_rna(bp[4]);
                mma8(acc[0][nt], a[0], b0, b1);
                mma8(acc[1][nt], a[1], b0, b1);
            }
        }
    }

    // epilogue: Q scaled; all outputs tf32-exact; permuted layouts.
    const float SC = (float)(1.4426950408889634 / 32.0);
#pragma unroll
    for (int mt = 0; mt < 2; mt++) {
#pragma unroll
        for (int nt = 0; nt < 12; nt++) {
            int col = wn * 96 + nt * 8 + 2 * (lane & 3);
            int row = m0 + wm * 32 + mt * 16 + (lane >> 2);
            if (col < 128) {
                float* outp = (col < 64) ? g_Q : g_K;
                float sc = (col < 64) ? SC : 1.0f;
                int b8  = (col & 63) & ~7;
                int p0  = b8 | perm8(col & 7);
                int p1  = b8 | perm8((col + 1) & 7);
                outp[(size_t)row * DK + p0]       = tf32ef(acc[mt][nt][0] * sc);
                outp[(size_t)row * DK + p1]       = tf32ef(acc[mt][nt][1] * sc);
                outp[(size_t)(row + 8) * DK + p0] = tf32ef(acc[mt][nt][2] * sc);
                outp[(size_t)(row + 8) * DK + p1] = tf32ef(acc[mt][nt][3] * sc);
            } else {
                int lc = col & 63;
                int b0r = row >> 12,  s0 = row & 4095;
                int b1r = (row + 8) >> 12, s1 = (row + 8) & 4095;
                size_t pt0 = (size_t)(s0 & ~7) | perm8(s0 & 7);
                size_t pt1 = (size_t)(s1 & ~7) | perm8(s1 & 7);
                g_V[((size_t)b0r * 64 + lc)     * 4096 + pt0] = tf32ef(acc[mt][nt][0]);
                g_V[((size_t)b0r * 64 + lc + 1) * 4096 + pt0] = tf32ef(acc[mt][nt][1]);
                g_V[((size_t)b1r * 64 + lc)     * 4096 + pt1] = tf32ef(acc[mt][nt][2]);
                g_V[((size_t)b1r * 64 + lc + 1) * 4096 + pt1] = tf32ef(acc[mt][nt][3]);
            }
        }
    }
}

// ---------------------------------------------------------------------------
// Phase 2: flash attention, split-KV per-warp accumulators.
// 512 thr = 8 row-groups x 2 kv-halves; warp 16 q-rows x 64 kv cols with
// private (m,l,O). ONE __syncthreads per kv-tile. Halves merged per q-tile
// via exact LSE combine. P smem interleaved (STS.128 / LDS.64).
// ---------------------------------------------------------------------------
constexpr int KSZ  = 128 * 72;
constexpr int VTSZ = 64 * 136;
constexpr int STG  = KSZ + VTSZ;
constexpr int POFF = 2 * STG;
constexpr int PSZ  = 64 * 264;
constexpr int ATTN_SMEM = (POFF + PSZ) * 4;   // 210944 B

__global__ __launch_bounds__(512, 1)
void attn_kernel(float* __restrict__ out)
{
    extern __shared__ float sm[];
    __shared__ float Xm[128];
    __shared__ float Xl[128];

    const int b    = blockIdx.y;
    const int pj   = blockIdx.x;
    const int tid  = threadIdx.x;
    const int lane = tid & 31;
    const int warp = tid >> 5;
    const int wr   = warp >> 1;
    const int wc   = warp & 1;
    const int wb   = wr * 16;
    const int kb   = wc * 64;
    const int p4   = lane >> 2;
    const int q4   = lane & 3;
    const int RB   = p4 + wr * 8;

    float* Ps = sm + POFF;

    auto load_kv = [&](int kt, int st) {
        float* Ks  = sm + st * STG;
        float* VTs = Ks + KSZ;
        const int t0 = kt * 128;
#pragma unroll
        for (int p = 0; p < 4; p++) {
            int c = tid + p * 512;
            int t = c >> 4, seg = c & 15;
            cpa16(Ks + t * 72 + seg * 4,
                  g_K + ((size_t)(b * S + t0 + t)) * 64 + seg * 4);
        }
#pragma unroll
        for (int p = 0; p < 4; p++) {
            int c = tid + p * 512;
            int dk = c >> 5, ch = c & 31;
            cpa16(VTs + dk * 136 + ch * 4,
                  g_V + ((size_t)b * 64 + dk) * 4096 + t0 + ch * 4);
        }
        CPA_COMMIT();
    };

    for (int qsel = 0; qsel < 2; qsel++) {
        const int qt = qsel ? (31 - pj) : pj;
        const int q0 = qt * 128;
        const int nt = qt + 1;

        load_kv(0, 0);

        uint32_t qa[8][4];
#pragma unroll
        for (int s = 0; s < 8; s++) {
            const float* qp = g_Q + ((size_t)(b * S + q0 + wb + p4)) * 64 + s * 8 + 2 * q4;
            float2 lo = *(const float2*)qp;
            float2 hi = *(const float2*)(qp + 8 * 64);
            qa[s][0] = f2u(lo.x);
            qa[s][1] = f2u(hi.x);
            qa[s][2] = f2u(lo.y);
            qa[s][3] = f2u(hi.y);
        }

        float of[8][4];
        float m0r = NEG, m1r = NEG, l0 = 0.0f, l1 = 0.0f;
#pragma unroll
        for (int j = 0; j < 8; j++)
#pragma unroll
            for (int e = 0; e < 4; e++) of[j][e] = 0.0f;

        for (int it = 0; it < nt; ++it) {
            const int st = it & 1;
            cpa_wait<0>();
            __syncthreads();                  // ONLY barrier per tile
            if (it + 1 < nt) load_kv(it + 1, st ^ 1);

            const float* Ks  = sm + st * STG;
            const float* VTs = Ks + KSZ;

            // ---- S = Q K^T ----
            float sf[8][4];
#pragma unroll
            for (int j = 0; j < 8; j++)
#pragma unroll
                for (int e = 0; e < 4; e++) sf[j][e] = 0.0f;

            const float* kB = Ks + (kb + p4) * 72 + 2 * q4;
#pragma unroll
            for (int s = 0; s < 8; s++) {
                const float* kp = kB + s * 8;
#pragma unroll
                for (int j = 0; j < 8; j++) {
                    float2 kv2 = *(const float2*)(kp + j * 8 * 72);
                    mma8(sf[j], qa[s], f2u(kv2.x), f2u(kv2.y));
                }
            }

            // ---- causal mask (diagonal tile) ----
            if (it == qt) {
                int r0 = wb + p4;
#pragma unroll
                for (int j = 0; j < 8; j++) {
                    int c0 = kb + j * 8 + 2 * q4;
                    if (c0     > r0)     sf[j][0] = NEG;
                    if (c0 + 1 > r0)     sf[j][1] = NEG;
                    if (c0     > r0 + 8) sf[j][2] = NEG;
                    if (c0 + 1 > r0 + 8) sf[j][3] = NEG;
                }
            }

            // ---- warp-local online softmax (private m,l) ----
            float mx0 = NEG, mx1 = NEG;
#pragma unroll
            for (int j = 0; j < 8; j++) {
                mx0 = fmaxf(mx0, fmaxf(sf[j][0], sf[j][1]));
                mx1 = fmaxf(mx1, fmaxf(sf[j][2], sf[j][3]));
            }
            mx0 = fmaxf(mx0, __shfl_xor_sync(0xffffffffu, mx0, 1));
            mx0 = fmaxf(mx0, __shfl_xor_sync(0xffffffffu, mx0, 2));
            mx1 = fmaxf(mx1, __shfl_xor_sync(0xffffffffu, mx1, 1));
            mx1 = fmaxf(mx1, __shfl_xor_sync(0xffffffffu, mx1, 2));
            float mn0 = fmaxf(m0r, mx0), mn1 = fmaxf(m1r, mx1);
            float al0 = ex2f(m0r - mn0), al1 = ex2f(m1r - mn1);
            float keep0 = (mn0 > -1e29f) ? 1.0f : 0.0f;   // fully-masked guard
            float keep1 = (mn1 > -1e29f) ? 1.0f : 0.0f;
            m0r = mn0; m1r = mn1;

            float rs0 = 0.0f, rs1 = 0.0f;
            float* pw = Ps + RB * 264 + (kb + 2 * q4) * 2;
#pragma unroll
            for (int j = 0; j < 8; j++) {
                float p00 = tf32ef(ex2f(sf[j][0] - mn0)) * keep0;
                float p01 = tf32ef(ex2f(sf[j][1] - mn0)) * keep0;
                float p10 = tf32ef(ex2f(sf[j][2] - mn1)) * keep1;
                float p11 = tf32ef(ex2f(sf[j][3] - mn1)) * keep1;
                rs0 += p00 + p01;
                rs1 += p10 + p11;
                *(float4*)(pw + j * 16) = make_float4(p00, p10, p01, p11);
            }
            rs0 += __shfl_xor_sync(0xffffffffu, rs0, 1);
            rs0 += __shfl_xor_sync(0xffffffffu, rs0, 2);
            rs1 += __shfl_xor_sync(0xffffffffu, rs1, 1);
            rs1 += __shfl_xor_sync(0xffffffffu, rs1, 2);
            l0 = l0 * al0 + rs0;
            l1 = l1 * al1 + rs1;
#pragma unroll
            for (int j = 0; j < 8; j++) {
                of[j][0] *= al0; of[j][1] *= al0;
                of[j][2] *= al1; of[j][3] *= al1;
            }

            // ---- O += P V over own kv half (all warp-private) ----
            const float* pA = Ps + RB * 264 + (kb + q4) * 2;
            const float* vB = VTs + p4 * 136 + kb + 2 * q4;
#pragma unroll
            for (int s2 = 0; s2 < 8; s2++) {
                uint32_t pa[4];
                float2 pa01 = *(const float2*)(pA + s2 * 16);
                float2 pa23 = *(const float2*)(pA + s2 * 16 + 8);
                pa[0] = f2u(pa01.x); pa[1] = f2u(pa01.y);
                pa[2] = f2u(pa23.x); pa[3] = f2u(pa23.y);
                const float* vp = vB + s2 * 8;
#pragma unroll
                for (int j2 = 0; j2 < 8; j2++) {
                    float2 vv = *(const float2*)(vp + j2 * 8 * 136);
                    mma8(of[j2], pa, f2u(vv.x), f2u(vv.y));
                }
            }
        }

        // ---- merge halves once per q-tile (exact LSE combine) ----
        __syncthreads();
        if (wc == 1) {
            float* cb = Ps + (wb + p4) * 132 + 2 * q4;
#pragma unroll
            for (int j2 = 0; j2 < 8; j2++) {
                *(float2*)(cb + j2 * 8)           = make_float2(of[j2][0], of[j2][1]);
                *(float2*)(cb + 8 * 132 + j2 * 8) = make_float2(of[j2][2], of[j2][3]);
            }
            if (q4 == 0) {
                Xm[wb + p4]     = m0r;  Xl[wb + p4]     = l0;
                Xm[wb + p4 + 8] = m1r;  Xl[wb + p4 + 8] = l1;
            }
        }
        __syncthreads();
        if (wc == 0) {
            float mo0 = Xm[wb + p4],     lo0 = Xl[wb + p4];
            float mo1 = Xm[wb + p4 + 8], lo1 = Xl[wb + p4 + 8];
            float mg0 = fmaxf(m0r, mo0), mg1 = fmaxf(m1r, mo1);
            float s0 = ex2f(m0r - mg0), t0 = ex2f(mo0 - mg0);
            float s1 = ex2f(m1r - mg1), t1 = ex2f(mo1 - mg1);
            float inv0 = 1.0f / (l0 * s0 + lo0 * t0);
            float inv1 = 1.0f / (l1 * s1 + lo1 * t1);
            const float* cb = Ps + (wb + p4) * 132 + 2 * q4;
            float* orow0 = out + ((size_t)(b * S + q0 + wb + p4)) * 64 + 2 * q4;
            float* orow1 = orow0 + 8 * 64;
#pragma unroll
            for (int j2 = 0; j2 < 8; j2++) {
                float2 c0 = *(const float2*)(cb + j2 * 8);
                float2 c1 = *(const float2*)(cb + 8 * 132 + j2 * 8);
                *(float2*)(orow0 + j2 * 8) =
                    make_float2((of[j2][0] * s0 + c0.x * t0) * inv0,
                                (of[j2][1] * s0 + c0.y * t0) * inv0);
                *(float2*)(orow1 + j2 * 8) =
                    make_float2((of[j2][2] * s1 + c1.x * t1) * inv1,
                                (of[j2][3] * s1 + c1.y * t1) * inv1);
            }
        }
        __syncthreads();
    }
}

// ---------------------------------------------------------------------------
extern "C" void kernel_launch(void* const* d_in, const int* in_sizes, int n_in,
                              void* d_out, int out_size)
{
    const float* x  = (const float*)d_in[0];
    const float* wq = (const float*)d_in[1];
    const float* wk = (const float*)d_in[2];
    const float* wv = (const float*)d_in[3];
    float* out = (float*)d_out;

    cudaFuncSetAttribute(proj_kernel,
                         cudaFuncAttributeMaxDynamicSharedMemorySize, PROJ_SMEM);
    cudaFuncSetAttribute(attn_kernel,
                         cudaFuncAttributeMaxDynamicSharedMemorySize, ATTN_SMEM);

    proj_kernel<<<M / 256, 512, PROJ_SMEM>>>(x, wq, wk, wv);
    attn_kernel<<<dim3(16, B), 512, ATTN_SMEM>>>(out);
}

// round 9
// speedup vs baseline: 1.3487x; 1.0188x over previous
#include <cuda_runtime.h>
#include <cstdint>

// ---------------------------------------------------------------------------
// AttentionHead  B=8 S=4096 D=1024 DK=64
// Round 9: register-resident P. K rows stored into smem at pair-permuted
// slots so the exp'd S C-fragment IS the PV A-fragment (regs {c0,c2,c1,c3}).
// P smem round-trip (8 STS.128 + 16 LDS.64 per warp/tile) deleted exactly.
// ---------------------------------------------------------------------------

constexpr int B  = 8;
constexpr int S  = 4096;
constexpr int D  = 1024;
constexpr int DK = 64;
constexpr int M  = B * S;

__device__ float g_Q[M * DK];
__device__ float g_K[M * DK];
__device__ float g_V[M * DK];   // used as [B][64][4096], t pair-permuted

__device__ __forceinline__ float ex2f(float x) {
    float y; asm("ex2.approx.ftz.f32 %0, %1;" : "=f"(y) : "f"(x)); return y;
}
__device__ __forceinline__ uint32_t tf32_rna(float f) {
    uint32_t u; asm("cvt.rna.tf32.f32 %0, %1;" : "=r"(u) : "f"(f)); return u;
}
__device__ __forceinline__ float tf32ef(float f) {
    return __uint_as_float(tf32_rna(f));
}
__device__ __forceinline__ uint32_t f2u(float f) { return __float_as_uint(f); }

// pair permutation within an 8-group: (u,u+4) -> (2u, 2u+1)
__host__ __device__ __forceinline__ int perm8(int u) {
    return 2 * (u & 3) + ((u >> 2) & 1);
}

__device__ __forceinline__ void cpa16(void* dst_smem, const void* src) {
    uint32_t a;
    asm("{ .reg .u64 t; cvta.to.shared.u64 t, %1; cvt.u32.u64 %0, t; }"
        : "=r"(a) : "l"(dst_smem));
    asm volatile("cp.async.cg.shared.global [%0], [%1], 16;" :: "r"(a), "l"(src));
}
#define CPA_COMMIT() asm volatile("cp.async.commit_group;" ::: "memory")
template <int N>
__device__ __forceinline__ void cpa_wait() {
    asm volatile("cp.async.wait_group %0;" :: "n"(N) : "memory");
}

// m16n8k8 tf32 HMMA. A row-major frag, B col-major frag, f32 accum.
__device__ __forceinline__ void mma8(float c[4], const uint32_t a[4],
                                     uint32_t b0, uint32_t b1) {
    asm volatile(
        "mma.sync.aligned.m16n8k8.row.col.f32.tf32.tf32.f32 "
        "{%0,%1,%2,%3}, {%4,%5,%6,%7}, {%8,%9}, {%0,%1,%2,%3};"
        : "+f"(c[0]), "+f"(c[1]), "+f"(c[2]), "+f"(c[3])
        : "r"(a[0]), "r"(a[1]), "r"(a[2]), "r"(a[3]), "r"(b0), "r"(b1));
}

constexpr float NEG = -1e30f;

// ---------------------------------------------------------------------------
// Phase 1: C[M,192] = X[M,1024] @ [wQ|wK|wV]^T   (unchanged from R8)
// ---------------------------------------------------------------------------
constexpr int PXS = 256 * 36;
constexpr int PWS = 192 * 36;
constexpr int PSTG = PXS + PWS;
constexpr int PROJ_SMEM = 2 * PSTG * 4;       // 129024 B

__global__ __launch_bounds__(512, 1)
void proj_kernel(const float* __restrict__ x,
                 const float* __restrict__ wq,
                 const float* __restrict__ wk,
                 const float* __restrict__ wv)
{
    extern __shared__ float ps[];
    const int tid  = threadIdx.x;
    const int lane = tid & 31;
    const int warp = tid >> 5;
    const int wm   = warp & 7;
    const int wn   = warp >> 3;
    const int m0   = blockIdx.x * 256;

    auto load_stage = [&](int st, int k0) {
        float* xs = ps + st * PSTG;
        float* ws = xs + PXS;
#pragma unroll
        for (int p = 0; p < 4; p++) {
            int c = tid + p * 512;
            int t = c >> 3, seg = c & 7;
            cpa16(xs + t * 36 + seg * 4, x + (size_t)(m0 + t) * D + k0 + seg * 4);
        }
#pragma unroll
        for (int p = 0; p < 3; p++) {
            int c = tid + p * 512;
            int n = c >> 3, seg = c & 7;
            const float* w = (n < 64) ? wq : (n < 128) ? wk : wv;
            cpa16(ws + n * 36 + seg * 4, w + (size_t)(n & 63) * D + k0 + seg * 4);
        }
        CPA_COMMIT();
    };

    float acc[2][12][4];
#pragma unroll
    for (int mt = 0; mt < 2; mt++)
#pragma unroll
        for (int nt = 0; nt < 12; nt++)
#pragma unroll
            for (int e = 0; e < 4; e++) acc[mt][nt][e] = 0.0f;

    load_stage(0, 0);

    for (int it = 0; it < 32; ++it) {
        cpa_wait<0>();
        __syncthreads();
        if (it + 1 < 32) load_stage((it + 1) & 1, (it + 1) * 32);

        const float* xs = ps + (it & 1) * PSTG;
        const float* ws = xs + PXS;
        const float* aB = xs + (wm * 32 + (lane >> 2)) * 36 + (lane & 3);
        const float* bB = ws + (wn * 96 + (lane >> 2)) * 36 + (lane & 3);

#pragma unroll
        for (int s = 0; s < 4; s++) {
            uint32_t a[2][4];
#pragma unroll
            for (int mt = 0; mt < 2; mt++) {
                const float* ap = aB + mt * 16 * 36 + s * 8;
                a[mt][0] = tf32_rna(ap[0]);
                a[mt][1] = tf32_rna(ap[8 * 36]);
                a[mt][2] = tf32_rna(ap[4]);
                a[mt][3] = tf32_rna(ap[8 * 36 + 4]);
            }
#pragma unroll
            for (int nt = 0; nt < 12; nt++) {
                const float* bp = bB + nt * 8 * 36 + s * 8;
                uint32_t b0 = tf32_rna(bp[0]);
                uint32_t b1 = tf32_rna(bp[4]);
                mma8(acc[0][nt], a[0], b0, b1);
                mma8(acc[1][nt], a[1], b0, b1);
            }
        }
    }

    const float SC = (float)(1.4426950408889634 / 32.0);
#pragma unroll
    for (int mt = 0; mt < 2; mt++) {
#pragma unroll
        for (int nt = 0; nt < 12; nt++) {
            int col = wn * 96 + nt * 8 + 2 * (lane & 3);
            int row = m0 + wm * 32 + mt * 16 + (lane >> 2);
            if (col < 128) {
                float* outp = (col < 64) ? g_Q : g_K;
                float sc = (col < 64) ? SC : 1.0f;
                int b8  = (col & 63) & ~7;
                int p0  = b8 | perm8(col & 7);
                int p1  = b8 | perm8((col + 1) & 7);
                outp[(size_t)row * DK + p0]       = tf32ef(acc[mt][nt][0] * sc);
                outp[(size_t)row * DK + p1]       = tf32ef(acc[mt][nt][1] * sc);
                outp[(size_t)(row + 8) * DK + p0] = tf32ef(acc[mt][nt][2] * sc);
                outp[(size_t)(row + 8) * DK + p1] = tf32ef(acc[mt][nt][3] * sc);
            } else {
                int lc = col & 63;
                int b0r = row >> 12,  s0 = row & 4095;
                int b1r = (row + 8) >> 12, s1 = (row + 8) & 4095;
                size_t pt0 = (size_t)(s0 & ~7) | perm8(s0 & 7);
                size_t pt1 = (size_t)(s1 & ~7) | perm8(s1 & 7);
                g_V[((size_t)b0r * 64 + lc)     * 4096 + pt0] = tf32ef(acc[mt][nt][0]);
                g_V[((size_t)b0r * 64 + lc + 1) * 4096 + pt0] = tf32ef(acc[mt][nt][1]);
                g_V[((size_t)b1r * 64 + lc)     * 4096 + pt1] = tf32ef(acc[mt][nt][2]);
                g_V[((size_t)b1r * 64 + lc + 1) * 4096 + pt1] = tf32ef(acc[mt][nt][3]);
            }
        }
    }
}

// ---------------------------------------------------------------------------
// Phase 2: flash attention, register-resident P.
// K smem rows at pair-permuted slots (kv t -> slot (t&~7)|perm8(t&7));
// S slot-cols {2q4,2q4+1} == original kv {q4,q4+4} == PV A-frag k indices.
// VT smem [dk][t_perm] unchanged. ONE barrier per kv-tile.
// ---------------------------------------------------------------------------
constexpr int KSZ  = 128 * 72;
constexpr int VTSZ = 64 * 136;
constexpr int STG  = KSZ + VTSZ;
constexpr int COFF = 2 * STG;                 // merge scratch
constexpr int CSZ  = 128 * 132;
constexpr int ATTN_SMEM = (COFF + CSZ) * 4;   // 210944 B

__global__ __launch_bounds__(512, 1)
void attn_kernel(float* __restrict__ out)
{
    extern __shared__ float sm[];
    __shared__ float Xm[128];
    __shared__ float Xl[128];

    const int b    = blockIdx.y;
    const int pj   = blockIdx.x;
    const int tid  = threadIdx.x;
    const int lane = tid & 31;
    const int warp = tid >> 5;
    const int wr   = warp >> 1;
    const int wc   = warp & 1;
    const int wb   = wr * 16;
    const int kb   = wc * 64;
    const int p4   = lane >> 2;
    const int q4   = lane & 3;

    float* Cs = sm + COFF;

    auto load_kv = [&](int kt, int st) {
        float* Ks  = sm + st * STG;
        float* VTs = Ks + KSZ;
        const int t0 = kt * 128;
#pragma unroll
        for (int p = 0; p < 4; p++) {         // K rows -> pair-permuted slots
            int c = tid + p * 512;
            int t = c >> 4, seg = c & 15;
            int slot = (t & ~7) | perm8(t & 7);
            cpa16(Ks + slot * 72 + seg * 4,
                  g_K + ((size_t)(b * S + t0 + t)) * 64 + seg * 4);
        }
#pragma unroll
        for (int p = 0; p < 4; p++) {         // VT: 64 dk-rows x 128 t (perm in gmem)
            int c = tid + p * 512;
            int dk = c >> 5, ch = c & 31;
            cpa16(VTs + dk * 136 + ch * 4,
                  g_V + ((size_t)b * 64 + dk) * 4096 + t0 + ch * 4);
        }
        CPA_COMMIT();
    };

    for (int qsel = 0; qsel < 2; qsel++) {
        const int qt = qsel ? (31 - pj) : pj;
        const int q0 = qt * 128;
        const int nt = qt + 1;

        load_kv(0, 0);

        uint32_t qa[8][4];
#pragma unroll
        for (int s = 0; s < 8; s++) {
            const float* qp = g_Q + ((size_t)(b * S + q0 + wb + p4)) * 64 + s * 8 + 2 * q4;
            float2 lo = *(const float2*)qp;
            float2 hi = *(const float2*)(qp + 8 * 64);
            qa[s][0] = f2u(lo.x);
            qa[s][1] = f2u(hi.x);
            qa[s][2] = f2u(lo.y);
            qa[s][3] = f2u(hi.y);
        }

        float of[8][4];
        float m0r = NEG, m1r = NEG, l0 = 0.0f, l1 = 0.0f;
#pragma unroll
        for (int j = 0; j < 8; j++)
#pragma unroll
            for (int e = 0; e < 4; e++) of[j][e] = 0.0f;

        for (int it = 0; it < nt; ++it) {
            const int st = it & 1;
            cpa_wait<0>();
            __syncthreads();                  // only barrier per tile
            if (it + 1 < nt) load_kv(it + 1, st ^ 1);

            const float* Ks  = sm + st * STG;
            const float* VTs = Ks + KSZ;

            // ---- S = Q K^T  (slot-column space) ----
            float sf[8][4];
#pragma unroll
            for (int j = 0; j < 8; j++)
#pragma unroll
                for (int e = 0; e < 4; e++) sf[j][e] = 0.0f;

            const float* kB = Ks + (kb + p4) * 72 + 2 * q4;
#pragma unroll
            for (int s = 0; s < 8; s++) {
                const float* kp = kB + s * 8;
#pragma unroll
                for (int j = 0; j < 8; j++) {
                    float2 kv2 = *(const float2*)(kp + j * 8 * 72);
                    mma8(sf[j], qa[s], f2u(kv2.x), f2u(kv2.y));
                }
            }

            // ---- causal mask (slot -> original kv: c0/c2 -> q4, c1/c3 -> q4+4)
            if (it == qt) {
                int r0 = wb + p4;
#pragma unroll
                for (int j = 0; j < 8; j++) {
                    int ta = kb + j * 8 + q4;       // original kv of c0/c2
                    int tb = ta + 4;                // original kv of c1/c3
                    if (ta > r0)     sf[j][0] = NEG;
                    if (tb > r0)     sf[j][1] = NEG;
                    if (ta > r0 + 8) sf[j][2] = NEG;
                    if (tb > r0 + 8) sf[j][3] = NEG;
                }
            }

            // ---- warp-local online softmax; P stays in registers ----
            float mx0 = NEG, mx1 = NEG;
#pragma unroll
            for (int j = 0; j < 8; j++) {
                mx0 = fmaxf(mx0, fmaxf(sf[j][0], sf[j][1]));
                mx1 = fmaxf(mx1, fmaxf(sf[j][2], sf[j][3]));
            }
            mx0 = fmaxf(mx0, __shfl_xor_sync(0xffffffffu, mx0, 1));
            mx0 = fmaxf(mx0, __shfl_xor_sync(0xffffffffu, mx0, 2));
            mx1 = fmaxf(mx1, __shfl_xor_sync(0xffffffffu, mx1, 1));
            mx1 = fmaxf(mx1, __shfl_xor_sync(0xffffffffu, mx1, 2));
            float mn0 = fmaxf(m0r, mx0), mn1 = fmaxf(m1r, mx1);
            float al0 = ex2f(m0r - mn0), al1 = ex2f(m1r - mn1);
            float keep0 = (mn0 > -1e29f) ? 1.0f : 0.0f;
            float keep1 = (mn1 > -1e29f) ? 1.0f : 0.0f;
            m0r = mn0; m1r = mn1;

            float rs0 = 0.0f, rs1 = 0.0f;
#pragma unroll
            for (int j = 0; j < 8; j++) {
                sf[j][0] = tf32ef(ex2f(sf[j][0] - mn0)) * keep0;
                sf[j][1] = tf32ef(ex2f(sf[j][1] - mn0)) * keep0;
                sf[j][2] = tf32ef(ex2f(sf[j][2] - mn1)) * keep1;
                sf[j][3] = tf32ef(ex2f(sf[j][3] - mn1)) * keep1;
                rs0 += sf[j][0] + sf[j][1];
                rs1 += sf[j][2] + sf[j][3];
            }
            rs0 += __shfl_xor_sync(0xffffffffu, rs0, 1);
            rs0 += __shfl_xor_sync(0xffffffffu, rs0, 2);
            rs1 += __shfl_xor_sync(0xffffffffu, rs1, 1);
            rs1 += __shfl_xor_sync(0xffffffffu, rs1, 2);
            l0 = l0 * al0 + rs0;
            l1 = l1 * al1 + rs1;
#pragma unroll
            for (int j = 0; j < 8; j++) {
                of[j][0] *= al0; of[j][1] *= al0;
                of[j][2] *= al1; of[j][3] *= al1;
            }

            // ---- O += P V : A-frag = exp'd C-frag {c0,c2,c1,c3} ----
            const float* vB = VTs + p4 * 136 + kb + 2 * q4;
#pragma unroll
            for (int s2 = 0; s2 < 8; s2++) {
                uint32_t pa[4];
                pa[0] = f2u(sf[s2][0]);
                pa[1] = f2u(sf[s2][2]);
                pa[2] = f2u(sf[s2][1]);
                pa[3] = f2u(sf[s2][3]);
                const float* vp = vB + s2 * 8;
#pragma unroll
                for (int j2 = 0; j2 < 8; j2++) {
                    float2 vv = *(const float2*)(vp + j2 * 8 * 136);
                    mma8(of[j2], pa, f2u(vv.x), f2u(vv.y));
                }
            }
        }

        // ---- merge halves once per q-tile (exact LSE combine) ----
        __syncthreads();
        if (wc == 1) {
            float* cb = Cs + (wb + p4) * 132 + 2 * q4;
#pragma unroll
            for (int j2 = 0; j2 < 8; j2++) {
                *(float2*)(cb + j2 * 8)           = make_float2(of[j2][0], of[j2][1]);
                *(float2*)(cb + 8 * 132 + j2 * 8) = make_float2(of[j2][2], of[j2][3]);
            }
            if (q4 == 0) {
                Xm[wb + p4]     = m0r;  Xl[wb + p4]     = l0;
                Xm[wb + p4 + 8] = m1r;  Xl[wb + p4 + 8] = l1;
            }
        }
        __syncthreads();
        if (wc == 0) {
            float mo0 = Xm[wb + p4],     lo0 = Xl[wb + p4];
            float mo1 = Xm[wb + p4 + 8], lo1 = Xl[wb + p4 + 8];
            float mg0 = fmaxf(m0r, mo0), mg1 = fmaxf(m1r, mo1);
            float s0 = ex2f(m0r - mg0), t0 = ex2f(mo0 - mg0);
            float s1 = ex2f(m1r - mg1), t1 = ex2f(mo1 - mg1);
            float inv0 = 1.0f / (l0 * s0 + lo0 * t0);
            float inv1 = 1.0f / (l1 * s1 + lo1 * t1);
            const float* cb = Cs + (wb + p4) * 132 + 2 * q4;
            float* orow0 = out + ((size_t)(b * S + q0 + wb + p4)) * 64 + 2 * q4;
            float* orow1 = orow0 + 8 * 64;
#pragma unroll
            for (int j2 = 0; j2 < 8; j2++) {
                float2 c0 = *(const float2*)(cb + j2 * 8);
                float2 c1 = *(const float2*)(cb + 8 * 132 + j2 * 8);
                *(float2*)(orow0 + j2 * 8) =
                    make_float2((of[j2][0] * s0 + c0.x * t0) * inv0,
                                (of[j2][1] * s0 + c0.y * t0) * inv0);
                *(float2*)(orow1 + j2 * 8) =
                    make_float2((of[j2][2] * s1 + c1.x * t1) * inv1,
                                (of[j2][3] * s1 + c1.y * t1) * inv1);
            }
        }
        __syncthreads();
    }
}

// ---------------------------------------------------------------------------
extern "C" void kernel_launch(void* const* d_in, const int* in_sizes, int n_in,
                              void* d_out, int out_size)
{
    const float* x  = (const float*)d_in[0];
    const float* wq = (const float*)d_in[1];
    const float* wk = (const float*)d_in[2];
    const float* wv = (const float*)d_in[3];
    float* out = (float*)d_out;

    cudaFuncSetAttribute(proj_kernel,
                         cudaFuncAttributeMaxDynamicSharedMemorySize, PROJ_SMEM);
    cudaFuncSetAttribute(attn_kernel,
                         cudaFuncAttributeMaxDynamicSharedMemorySize, ATTN_SMEM);

    proj_kernel<<<M / 256, 512, PROJ_SMEM>>>(x, wq, wk, wv);
    attn_kernel<<<dim3(16, B), 512, ATTN_SMEM>>>(out);
}

// round 10
// speedup vs baseline: 1.4595x; 1.0821x over previous
#include <cuda_runtime.h>
#include <cstdint>

// ---------------------------------------------------------------------------
// AttentionHead  B=8 S=4096 D=1024 DK=64
// Round 10: de-lockstep. Halves = warps 0-7 / 8-15 (2 of each per SMSP),
// each half loads its own disjoint K/VT slice and syncs on a NAMED barrier,
// so the halves drift and softmax of one overlaps MMAs of the other.
// Within-warp exp->PV interleaving; exact skip of fully-masked diag quarters.
// ---------------------------------------------------------------------------

constexpr int B  = 8;
constexpr int S  = 4096;
constexpr int D  = 1024;
constexpr int DK = 64;
constexpr int M  = B * S;

__device__ float g_Q[M * DK];
__device__ float g_K[M * DK];
__device__ float g_V[M * DK];   // used as [B][64][4096], t pair-permuted

__device__ __forceinline__ float ex2f(float x) {
    float y; asm("ex2.approx.ftz.f32 %0, %1;" : "=f"(y) : "f"(x)); return y;
}
__device__ __forceinline__ uint32_t tf32_rna(float f) {
    uint32_t u; asm("cvt.rna.tf32.f32 %0, %1;" : "=r"(u) : "f"(f)); return u;
}
__device__ __forceinline__ float tf32ef(float f) {
    return __uint_as_float(tf32_rna(f));
}
__device__ __forceinline__ uint32_t f2u(float f) { return __float_as_uint(f); }

__host__ __device__ __forceinline__ int perm8(int u) {
    return 2 * (u & 3) + ((u >> 2) & 1);
}

__device__ __forceinline__ void cpa16(void* dst_smem, const void* src) {
    uint32_t a;
    asm("{ .reg .u64 t; cvta.to.shared.u64 t, %1; cvt.u32.u64 %0, t; }"
        : "=r"(a) : "l"(dst_smem));
    asm volatile("cp.async.cg.shared.global [%0], [%1], 16;" :: "r"(a), "l"(src));
}
#define CPA_COMMIT() asm volatile("cp.async.commit_group;" ::: "memory")
template <int N>
__device__ __forceinline__ void cpa_wait() {
    asm volatile("cp.async.wait_group %0;" :: "n"(N) : "memory");
}
#define BAR_SYNC(id) asm volatile("bar.sync %0, 256;" :: "r"(id) : "memory")

__device__ __forceinline__ void mma8(float c[4], const uint32_t a[4],
                                     uint32_t b0, uint32_t b1) {
    asm volatile(
        "mma.sync.aligned.m16n8k8.row.col.f32.tf32.tf32.f32 "
        "{%0,%1,%2,%3}, {%4,%5,%6,%7}, {%8,%9}, {%0,%1,%2,%3};"
        : "+f"(c[0]), "+f"(c[1]), "+f"(c[2]), "+f"(c[3])
        : "r"(a[0]), "r"(a[1]), "r"(a[2]), "r"(a[3]), "r"(b0), "r"(b1));
}

constexpr float NEG = -1e30f;

// ---------------------------------------------------------------------------
// Phase 1: C[M,192] = X[M,1024] @ [wQ|wK|wV]^T   (unchanged from R9)
// ---------------------------------------------------------------------------
constexpr int PXS = 256 * 36;
constexpr int PWS = 192 * 36;
constexpr int PSTG = PXS + PWS;
constexpr int PROJ_SMEM = 2 * PSTG * 4;

__global__ __launch_bounds__(512, 1)
void proj_kernel(const float* __restrict__ x,
                 const float* __restrict__ wq,
                 const float* __restrict__ wk,
                 const float* __restrict__ wv)
{
    extern __shared__ float ps[];
    const int tid  = threadIdx.x;
    const int lane = tid & 31;
    const int warp = tid >> 5;
    const int wm   = warp & 7;
    const int wn   = warp >> 3;
    const int m0   = blockIdx.x * 256;

    auto load_stage = [&](int st, int k0) {
        float* xs = ps + st * PSTG;
        float* ws = xs + PXS;
#pragma unroll
        for (int p = 0; p < 4; p++) {
            int c = tid + p * 512;
            int t = c >> 3, seg = c & 7;
            cpa16(xs + t * 36 + seg * 4, x + (size_t)(m0 + t) * D + k0 + seg * 4);
        }
#pragma unroll
        for (int p = 0; p < 3; p++) {
            int c = tid + p * 512;
            int n = c >> 3, seg = c & 7;
            const float* w = (n < 64) ? wq : (n < 128) ? wk : wv;
            cpa16(ws + n * 36 + seg * 4, w + (size_t)(n & 63) * D + k0 + seg * 4);
        }
        CPA_COMMIT();
    };

    float acc[2][12][4];
#pragma unroll
    for (int mt = 0; mt < 2; mt++)
#pragma unroll
        for (int nt = 0; nt < 12; nt++)
#pragma unroll
            for (int e = 0; e < 4; e++) acc[mt][nt][e] = 0.0f;

    load_stage(0, 0);

    for (int it = 0; it < 32; ++it) {
        cpa_wait<0>();
        __syncthreads();
        if (it + 1 < 32) load_stage((it + 1) & 1, (it + 1) * 32);

        const float* xs = ps + (it & 1) * PSTG;
        const float* ws = xs + PXS;
        const float* aB = xs + (wm * 32 + (lane >> 2)) * 36 + (lane & 3);
        const float* bB = ws + (wn * 96 + (lane >> 2)) * 36 + (lane & 3);

#pragma unroll
        for (int s = 0; s < 4; s++) {
            uint32_t a[2][4];
#pragma unroll
            for (int mt = 0; mt < 2; mt++) {
                const float* ap = aB + mt * 16 * 36 + s * 8;
                a[mt][0] = tf32_rna(ap[0]);
                a[mt][1] = tf32_rna(ap[8 * 36]);
                a[mt][2] = tf32_rna(ap[4]);
                a[mt][3] = tf32_rna(ap[8 * 36 + 4]);
            }
#pragma unroll
            for (int nt = 0; nt < 12; nt++) {
                const float* bp = bB + nt * 8 * 36 + s * 8;
                uint32_t b0 = tf32_rna(bp[0]);
                uint32_t b1 = tf32_rna(bp[4]);
                mma8(acc[0][nt], a[0], b0, b1);
                mma8(acc[1][nt], a[1], b0, b1);
            }
        }
    }

    const float SC = (float)(1.4426950408889634 / 32.0);
#pragma unroll
    for (int mt = 0; mt < 2; mt++) {
#pragma unroll
        for (int nt = 0; nt < 12; nt++) {
            int col = wn * 96 + nt * 8 + 2 * (lane & 3);
            int row = m0 + wm * 32 + mt * 16 + (lane >> 2);
            if (col < 128) {
                float* outp = (col < 64) ? g_Q : g_K;
                float sc = (col < 64) ? SC : 1.0f;
                int b8  = (col & 63) & ~7;
                int p0  = b8 | perm8(col & 7);
                int p1  = b8 | perm8((col + 1) & 7);
                outp[(size_t)row * DK + p0]       = tf32ef(acc[mt][nt][0] * sc);
                outp[(size_t)row * DK + p1]       = tf32ef(acc[mt][nt][1] * sc);
                outp[(size_t)(row + 8) * DK + p0] = tf32ef(acc[mt][nt][2] * sc);
                outp[(size_t)(row + 8) * DK + p1] = tf32ef(acc[mt][nt][3] * sc);
            } else {
                int lc = col & 63;
                int b0r = row >> 12,  s0 = row & 4095;
                int b1r = (row + 8) >> 12, s1 = (row + 8) & 4095;
                size_t pt0 = (size_t)(s0 & ~7) | perm8(s0 & 7);
                size_t pt1 = (size_t)(s1 & ~7) | perm8(s1 & 7);
                g_V[((size_t)b0r * 64 + lc)     * 4096 + pt0] = tf32ef(acc[mt][nt][0]);
                g_V[((size_t)b0r * 64 + lc + 1) * 4096 + pt0] = tf32ef(acc[mt][nt][1]);
                g_V[((size_t)b1r * 64 + lc)     * 4096 + pt1] = tf32ef(acc[mt][nt][2]);
                g_V[((size_t)b1r * 64 + lc + 1) * 4096 + pt1] = tf32ef(acc[mt][nt][3]);
            }
        }
    }
}

// ---------------------------------------------------------------------------
// Phase 2: flash attention, de-lockstepped halves.
// half = warp>>3 (warps 0-7 / 8-15): 2 warps of each half per SMSP.
// Each half loads only its disjoint slice (K slot rows kb..kb+63,
// VT cols kb..kb+63) and syncs on named barrier 1+half.
// ---------------------------------------------------------------------------
constexpr int KSZ  = 128 * 72;
constexpr int VTSZ = 64 * 136;
constexpr int STG  = KSZ + VTSZ;
constexpr int COFF = 2 * STG;
constexpr int CSZ  = 128 * 132;
constexpr int ATTN_SMEM = (COFF + CSZ) * 4;   // 210944 B

__global__ __launch_bounds__(512, 1)
void attn_kernel(float* __restrict__ out)
{
    extern __shared__ float sm[];
    __shared__ float Xm[128];
    __shared__ float Xl[128];

    const int b    = blockIdx.y;
    const int pj   = blockIdx.x;
    const int tid  = threadIdx.x;
    const int lane = tid & 31;
    const int warp = tid >> 5;
    const int wc   = warp >> 3;               // half: warps 0-7 | 8-15
    const int wr   = warp & 7;                // row group 0..7
    const int wb   = wr * 16;
    const int kb   = wc * 64;
    const int p4   = lane >> 2;
    const int q4   = lane & 3;
    const int htid = tid & 255;
    const int barid = 1 + wc;

    float* Cs = sm + COFF;

    // half-local cooperative load of this half's K/VT slice
    auto load_kv = [&](int kt, int st) {
        float* Ks  = sm + st * STG;
        float* VTs = Ks + KSZ;
        const int t0 = kt * 128;
#pragma unroll
        for (int p = 0; p < 4; p++) {         // K: 64 rows x 64 dk (slot-permuted)
            int c = htid + p * 256;
            int tl = c >> 4, seg = c & 15;
            int slot = kb + ((tl & ~7) | perm8(tl & 7));
            cpa16(Ks + slot * 72 + seg * 4,
                  g_K + ((size_t)(b * S + t0 + kb + tl)) * 64 + seg * 4);
        }
#pragma unroll
        for (int p = 0; p < 4; p++) {         // VT: 64 dk x 64 t (own cols)
            int c = htid + p * 256;
            int dk = c >> 4, ch = c & 15;
            cpa16(VTs + dk * 136 + kb + ch * 4,
                  g_V + ((size_t)b * 64 + dk) * 4096 + t0 + kb + ch * 4);
        }
        CPA_COMMIT();
    };

    for (int qsel = 0; qsel < 2; qsel++) {
        const int qt = qsel ? (31 - pj) : pj;
        const int q0 = qt * 128;
        const int nt = qt + 1;

        load_kv(0, 0);

        uint32_t qa[8][4];
#pragma unroll
        for (int s = 0; s < 8; s++) {
            const float* qp = g_Q + ((size_t)(b * S + q0 + wb + p4)) * 64 + s * 8 + 2 * q4;
            float2 lo = *(const float2*)qp;
            float2 hi = *(const float2*)(qp + 8 * 64);
            qa[s][0] = f2u(lo.x);
            qa[s][1] = f2u(hi.x);
            qa[s][2] = f2u(lo.y);
            qa[s][3] = f2u(hi.y);
        }

        float of[8][4];
        float m0r = NEG, m1r = NEG, l0 = 0.0f, l1 = 0.0f;
#pragma unroll
        for (int j = 0; j < 8; j++)
#pragma unroll
            for (int e = 0; e < 4; e++) of[j][e] = 0.0f;

        for (int it = 0; it < nt; ++it) {
            const int st = it & 1;
            cpa_wait<0>();
            BAR_SYNC(barid);                  // half-local barrier only
            if (it + 1 < nt) load_kv(it + 1, st ^ 1);

            // fully-masked diagonal quarter: exact no-op, skip compute
            if (it == qt && kb > wb + 15) continue;

            const float* Ks  = sm + st * STG;
            const float* VTs = Ks + KSZ;

            // ---- S = Q K^T (slot-column space) ----
            float sf[8][4];
#pragma unroll
            for (int j = 0; j < 8; j++)
#pragma unroll
                for (int e = 0; e < 4; e++) sf[j][e] = 0.0f;

            const float* kB = Ks + (kb + p4) * 72 + 2 * q4;
#pragma unroll
            for (int s = 0; s < 8; s++) {
                const float* kp = kB + s * 8;
#pragma unroll
                for (int j = 0; j < 8; j++) {
                    float2 kv2 = *(const float2*)(kp + j * 8 * 72);
                    mma8(sf[j], qa[s], f2u(kv2.x), f2u(kv2.y));
                }
            }

            // ---- causal mask (slot -> original kv) ----
            if (it == qt) {
                int r0 = wb + p4;
#pragma unroll
                for (int j = 0; j < 8; j++) {
                    int ta = kb + j * 8 + q4;
                    int tb = ta + 4;
                    if (ta > r0)     sf[j][0] = NEG;
                    if (tb > r0)     sf[j][1] = NEG;
                    if (ta > r0 + 8) sf[j][2] = NEG;
                    if (tb > r0 + 8) sf[j][3] = NEG;
                }
            }

            // ---- max reduce ----
            float mx0 = NEG, mx1 = NEG;
#pragma unroll
            for (int j = 0; j < 8; j++) {
                mx0 = fmaxf(mx0, fmaxf(sf[j][0], sf[j][1]));
                mx1 = fmaxf(mx1, fmaxf(sf[j][2], sf[j][3]));
            }
            mx0 = fmaxf(mx0, __shfl_xor_sync(0xffffffffu, mx0, 1));
            mx0 = fmaxf(mx0, __shfl_xor_sync(0xffffffffu, mx0, 2));
            mx1 = fmaxf(mx1, __shfl_xor_sync(0xffffffffu, mx1, 1));
            mx1 = fmaxf(mx1, __shfl_xor_sync(0xffffffffu, mx1, 2));
            float mn0 = fmaxf(m0r, mx0), mn1 = fmaxf(m1r, mx1);
            float al0 = ex2f(m0r - mn0), al1 = ex2f(m1r - mn1);
            float keep0 = (mn0 > -1e29f) ? 1.0f : 0.0f;
            float keep1 = (mn1 > -1e29f) ? 1.0f : 0.0f;
            m0r = mn0; m1r = mn1;
#pragma unroll
            for (int j = 0; j < 8; j++) {
                of[j][0] *= al0; of[j][1] *= al0;
                of[j][2] *= al1; of[j][3] *= al1;
            }

            // ---- exp interleaved with PV (A-frag = exp'd C-frag) ----
            float rs0 = 0.0f, rs1 = 0.0f;
            const float* vB = VTs + p4 * 136 + kb + 2 * q4;
#pragma unroll
            for (int s2 = 0; s2 < 8; s2++) {
                float p00 = tf32ef(ex2f(sf[s2][0] - mn0)) * keep0;
                float p01 = tf32ef(ex2f(sf[s2][1] - mn0)) * keep0;
                float p10 = tf32ef(ex2f(sf[s2][2] - mn1)) * keep1;
                float p11 = tf32ef(ex2f(sf[s2][3] - mn1)) * keep1;
                rs0 += p00 + p01;
                rs1 += p10 + p11;
                uint32_t pa[4];
                pa[0] = f2u(p00); pa[1] = f2u(p10);
                pa[2] = f2u(p01); pa[3] = f2u(p11);
                const float* vp = vB + s2 * 8;
#pragma unroll
                for (int j2 = 0; j2 < 8; j2++) {
                    float2 vv = *(const float2*)(vp + j2 * 8 * 136);
                    mma8(of[j2], pa, f2u(vv.x), f2u(vv.y));
                }
            }
            rs0 += __shfl_xor_sync(0xffffffffu, rs0, 1);
            rs0 += __shfl_xor_sync(0xffffffffu, rs0, 2);
            rs1 += __shfl_xor_sync(0xffffffffu, rs1, 1);
            rs1 += __shfl_xor_sync(0xffffffffu, rs1, 2);
            l0 = l0 * al0 + rs0;
            l1 = l1 * al1 + rs1;
        }

        // ---- merge halves once per q-tile (exact LSE combine) ----
        __syncthreads();
        if (wc == 1) {
            float* cb = Cs + (wb + p4) * 132 + 2 * q4;
#pragma unroll
            for (int j2 = 0; j2 < 8; j2++) {
                *(float2*)(cb + j2 * 8)           = make_float2(of[j2][0], of[j2][1]);
                *(float2*)(cb + 8 * 132 + j2 * 8) = make_float2(of[j2][2], of[j2][3]);
            }
            if (q4 == 0) {
                Xm[wb + p4]     = m0r;  Xl[wb + p4]     = l0;
                Xm[wb + p4 + 8] = m1r;  Xl[wb + p4 + 8] = l1;
            }
        }
        __syncthreads();
        if (wc == 0) {
            float mo0 = Xm[wb + p4],     lo0 = Xl[wb + p4];
            float mo1 = Xm[wb + p4 + 8], lo1 = Xl[wb + p4 + 8];
            float mg0 = fmaxf(m0r, mo0), mg1 = fmaxf(m1r, mo1);
            float s0 = ex2f(m0r - mg0), t0 = ex2f(mo0 - mg0);
            float s1 = ex2f(m1r - mg1), t1 = ex2f(mo1 - mg1);
            float inv0 = 1.0f / (l0 * s0 + lo0 * t0);
            float inv1 = 1.0f / (l1 * s1 + lo1 * t1);
            const float* cb = Cs + (wb + p4) * 132 + 2 * q4;
            float* orow0 = out + ((size_t)(b * S + q0 + wb + p4)) * 64 + 2 * q4;
            float* orow1 = orow0 + 8 * 64;
#pragma unroll
            for (int j2 = 0; j2 < 8; j2++) {
                float2 c0 = *(const float2*)(cb + j2 * 8);
                float2 c1 = *(const float2*)(cb + 8 * 132 + j2 * 8);
                *(float2*)(orow0 + j2 * 8) =
                    make_float2((of[j2][0] * s0 + c0.x * t0) * inv0,
                                (of[j2][1] * s0 + c0.y * t0) * inv0);
                *(float2*)(orow1 + j2 * 8) =
                    make_float2((of[j2][2] * s1 + c1.x * t1) * inv1,
                                (of[j2][3] * s1 + c1.y * t1) * inv1);
            }
        }
        __syncthreads();
    }
}

// ---------------------------------------------------------------------------
extern "C" void kernel_launch(void* const* d_in, const int* in_sizes, int n_in,
                              void* d_out, int out_size)
{
    const float* x  = (const float*)d_in[0];
    const float* wq = (const float*)d_in[1];
    const float* wk = (const float*)d_in[2];
    const float* wv = (const float*)d_in[3];
    float* out = (float*)d_out;

    cudaFuncSetAttribute(proj_kernel,
                         cudaFuncAttributeMaxDynamicSharedMemorySize, PROJ_SMEM);
    cudaFuncSetAttribute(attn_kernel,
                         cudaFuncAttributeMaxDynamicSharedMemorySize, ATTN_SMEM);

    proj_kernel<<<M / 256, 512, PROJ_SMEM>>>(x, wq, wk, wv);
    attn_kernel<<<dim3(16, B), 512, ATTN_SMEM>>>(out);
}